// round 2
// baseline (speedup 1.0000x reference)
#include <cuda_runtime.h>

// Node2VecModel: N=6 nodes, EMB=32.
// out[0..5]  = softplus(MLP(x))            (energy_output, fp32)
// out[6..12] = [0, sampled x5, 0] as float (path_indices)
//
// PRNG must bit-replicate JAX's *partitionable* threefry path (default since
// jax 0.4.30):
//   split(key, n):      keys[i] = threefry2x32(key, (0, i))    (full pair)
//   random_bits (32b):  bits[i] = o0 ^ o1, (o0,o1) = threefry2x32(key, (0, i))

#define NN   6
#define EMBD 32
#define H1   64
#define H2   32

__device__ __forceinline__ void tf2x32(unsigned k0, unsigned k1,
                                       unsigned x0, unsigned x1,
                                       unsigned &o0, unsigned &o1) {
    unsigned ks2 = k0 ^ k1 ^ 0x1BD11BDAu;
    x0 += k0; x1 += k1;
#define TF_RND(r) { x0 += x1; x1 = (x1 << (r)) | (x1 >> (32 - (r))); x1 ^= x0; }
    TF_RND(13) TF_RND(15) TF_RND(26) TF_RND(6)
    x0 += k1;  x1 += ks2 + 1u;
    TF_RND(17) TF_RND(29) TF_RND(16) TF_RND(24)
    x0 += ks2; x1 += k0 + 2u;
    TF_RND(13) TF_RND(15) TF_RND(26) TF_RND(6)
    x0 += k0;  x1 += k1 + 3u;
    TF_RND(17) TF_RND(29) TF_RND(16) TF_RND(24)
    x0 += k1;  x1 += ks2 + 4u;
    TF_RND(13) TF_RND(15) TF_RND(26) TF_RND(6)
    x0 += ks2; x1 += k0 + 5u;
#undef TF_RND
    o0 = x0; o1 = x1;
}

// JAX uniform(minval=tiny, maxval=1) -> gumbel, float32 path.
// floats = bitcast((bits>>9)|0x3f800000) - 1.0 ;
// (1-tiny) rounds to exactly 1.0f, so u = max(tiny, f + tiny).
__device__ __forceinline__ float gumbel_from_bits(unsigned b) {
    const float tiny = 1.1754943508222875e-38f;
    float f = __uint_as_float((b >> 9) | 0x3f800000u) - 1.0f;
    float u = fmaxf(__fadd_rn(f, tiny), tiny);
    return -logf(-logf(u));
}

__global__ void node2vec_kernel(const float* __restrict__ x,
                                const float* __restrict__ fc1_w, const float* __restrict__ fc1_b,
                                const float* __restrict__ fc2_w, const float* __restrict__ fc2_b,
                                const float* __restrict__ fc3_w, const float* __restrict__ fc3_b,
                                const float* __restrict__ pw,    const float* __restrict__ pb,
                                float* __restrict__ out) {
    __shared__ float sx[NN][EMBD];
    __shared__ float h1[NN][H1];
    __shared__ float h2[NN][H2];
    __shared__ float logp[NN][NN];

    int tid = threadIdx.x;

    // stage the tiny x into smem
    if (tid < NN * EMBD) sx[tid / EMBD][tid % EMBD] = x[tid];
    __syncthreads();

    // h1 = relu(x @ fc1_w + fc1_b)   [6,64] -> one elem per thread
    if (tid < NN * H1) {
        int i = tid / H1, j = tid % H1;
        float acc = fc1_b[j];
        #pragma unroll
        for (int k = 0; k < EMBD; k++) acc += sx[i][k] * fc1_w[k * H1 + j];
        h1[i][j] = fmaxf(acc, 0.0f);
    }
    __syncthreads();

    // h2 = relu(h1 @ fc2_w + fc2_b)  [6,32]
    if (tid < NN * H2) {
        int i = tid / H2, j = tid % H2;
        float acc = fc2_b[j];
        #pragma unroll
        for (int k = 0; k < H1; k++) acc += h1[i][k] * fc2_w[k * H2 + j];
        h2[i][j] = fmaxf(acc, 0.0f);
    }
    // logits = x @ path_fc_w + path_fc_b  [6,6] (independent; parallel thread slots)
    if (tid >= 192 && tid < 192 + NN * NN) {
        int t = tid - 192;
        int i = t / NN, j = t % NN;
        float acc = pb[j];
        #pragma unroll
        for (int k = 0; k < EMBD; k++) acc += sx[i][k] * pw[k * NN + j];
        logp[i][j] = acc;   // raw logits for now
    }
    __syncthreads();

    // energy = softplus(h2 @ fc3_w + fc3_b)  [6]
    if (tid < NN) {
        float acc = fc3_b[0];
        #pragma unroll
        for (int k = 0; k < H2; k++) acc += h2[tid][k] * fc3_w[k];
        // softplus = max(x,0) + log1p(exp(-|x|))
        out[tid] = fmaxf(acc, 0.0f) + log1pf(expf(-fabsf(acc)));
    }

    // log_softmax per row  [6,6]
    if (tid >= 32 && tid < 32 + NN) {
        int i = tid - 32;
        float m = logp[i][0];
        #pragma unroll
        for (int j = 1; j < NN; j++) m = fmaxf(m, logp[i][j]);
        float s = 0.0f;
        #pragma unroll
        for (int j = 0; j < NN; j++) s += expf(logp[i][j] - m);
        float lse = logf(s);
        #pragma unroll
        for (int j = 0; j < NN; j++) logp[i][j] = logp[i][j] - m - lse;
    }
    __syncthreads();

    // Sequential Gumbel-max sampling, thread 0 only.
    if (tid == 0) {
        // --- jax.random.split(key(42), 5), partitionable/foldlike mode ---
        // iota_2x32_shape((5,)): counts1 = 0, counts2 = i
        // keys[i] = full output pair of threefry2x32((0,42), (0, i))
        unsigned key0[NN - 1], key1[NN - 1];
        for (int i = 0; i < NN - 1; i++)
            tf2x32(0u, 42u, 0u, (unsigned)i, key0[i], key1[i]);

        bool mask[NN];
        mask[0] = false;
        #pragma unroll
        for (int j = 1; j < NN; j++) mask[j] = true;

        int cur = 0;
        out[NN] = 0.0f;            // path[0] = 0
        for (int step = 0; step < NN - 1; step++) {
            // random_bits(key, 32, (6,)) partitionable:
            // bits[j] = o0 ^ o1 with (o0,o1) = threefry2x32(key, (0, j))
            float best = -__int_as_float(0x7f800000);  // -inf
            int bestj = 0;
            bool have = false;
            #pragma unroll
            for (int j = 0; j < NN; j++) {
                if (!mask[j]) continue;               // where(mask,...,-inf)+g = -inf
                unsigned o0, o1;
                tf2x32(key0[step], key1[step], 0u, (unsigned)j, o0, o1);
                float v = logp[cur][j] + gumbel_from_bits(o0 ^ o1);
                if (!have || v > best) { best = v; bestj = j; have = true; }
            }
            cur = bestj;
            mask[bestj] = false;
            out[NN + 1 + step] = (float)bestj;
        }
        out[2 * NN] = 0.0f;        // path[N] = 0
    }
}

extern "C" void kernel_launch(void* const* d_in, const int* in_sizes, int n_in,
                              void* d_out, int out_size) {
    const float* x     = (const float*)d_in[0];
    // d_in[1] = path (int32, unused by the forward outputs)
    const float* fc1_w = (const float*)d_in[2];
    const float* fc1_b = (const float*)d_in[3];
    const float* fc2_w = (const float*)d_in[4];
    const float* fc2_b = (const float*)d_in[5];
    const float* fc3_w = (const float*)d_in[6];
    const float* fc3_b = (const float*)d_in[7];
    const float* pw    = (const float*)d_in[8];
    const float* pb    = (const float*)d_in[9];
    float* out = (float*)d_out;

    node2vec_kernel<<<1, 384>>>(x, fc1_w, fc1_b, fc2_w, fc2_b,
                                fc3_w, fc3_b, pw, pb, out);
}

// round 3
// speedup vs baseline: 1.5780x; 1.5780x over previous
#include <cuda_runtime.h>

// Node2VecModel: N=6, EMB=32. One tiny latency-bound kernel.
// out[0..5]  = softplus(MLP(x)); out[6..12] = [0, sampled x5, 0] as float.
//
// R3: parallelize threefry/gumbel across 30 threads (path-independent),
// prefetch weights to registers before first barrier, reduce thread-0 serial
// tail to masked argmax over a precomputed vall[step][cur][j] table.

#define NN   6
#define EMBD 32
#define H1   64
#define H2   32

__device__ __forceinline__ void tf2x32(unsigned k0, unsigned k1,
                                       unsigned x0, unsigned x1,
                                       unsigned &o0, unsigned &o1) {
    unsigned ks2 = k0 ^ k1 ^ 0x1BD11BDAu;
    x0 += k0; x1 += k1;
#define TF_RND(r) { x0 += x1; x1 = (x1 << (r)) | (x1 >> (32 - (r))); x1 ^= x0; }
    TF_RND(13) TF_RND(15) TF_RND(26) TF_RND(6)
    x0 += k1;  x1 += ks2 + 1u;
    TF_RND(17) TF_RND(29) TF_RND(16) TF_RND(24)
    x0 += ks2; x1 += k0 + 2u;
    TF_RND(13) TF_RND(15) TF_RND(26) TF_RND(6)
    x0 += k0;  x1 += k1 + 3u;
    TF_RND(17) TF_RND(29) TF_RND(16) TF_RND(24)
    x0 += k1;  x1 += ks2 + 4u;
    TF_RND(13) TF_RND(15) TF_RND(26) TF_RND(6)
    x0 += ks2; x1 += k0 + 5u;
#undef TF_RND
    o0 = x0; o1 = x1;
}

// JAX uniform(tiny, 1) float32 path -> gumbel. (1-tiny) rounds to 1.0f,
// so u = max(tiny, f + tiny) with f = bitcast((b>>9)|0x3f800000) - 1.
__device__ __forceinline__ float gumbel_from_bits(unsigned b) {
    const float tiny = 1.1754943508222875e-38f;
    float f = __uint_as_float((b >> 9) | 0x3f800000u) - 1.0f;
    float u = fmaxf(__fadd_rn(f, tiny), tiny);
    return -logf(-logf(u));
}

__global__ __launch_bounds__(384, 1)
void node2vec_kernel(const float* __restrict__ x,
                     const float* __restrict__ fc1_w, const float* __restrict__ fc1_b,
                     const float* __restrict__ fc2_w, const float* __restrict__ fc2_b,
                     const float* __restrict__ fc3_w, const float* __restrict__ fc3_b,
                     const float* __restrict__ pw,    const float* __restrict__ pb,
                     float* __restrict__ out) {
    __shared__ float sx[NN][EMBD];
    __shared__ float h1s[NN][H1];
    __shared__ float h2s[NN][H2];
    __shared__ float logp[NN][NN];
    __shared__ float g[NN - 1][NN];
    __shared__ float vall[NN - 1][NN][NN];

    int tid = threadIdx.x;

    // ---- prefetch (all LDGs issued before any barrier) ----
    int i1 = tid >> 6, j1 = tid & 63;         // h1 element (i1,j1), all 384 threads
    float w1[EMBD];
    #pragma unroll
    for (int k = 0; k < EMBD; k++) w1[k] = fc1_w[k * H1 + j1];
    float b1v = fc1_b[j1];

    int i2 = tid >> 5, j2 = tid & 31;         // h2 element, threads < 192
    float w2[H1];
    float b2v = 0.0f;
    if (tid < NN * H2) {
        #pragma unroll
        for (int k = 0; k < H1; k++) w2[k] = fc2_w[k * H2 + j2];
        b2v = fc2_b[j2];
    }

    float wp[EMBD];                           // path logits, threads 192..227
    float pbv = 0.0f;
    if (tid >= 192 && tid < 192 + NN * NN) {
        int jp = (tid - 192) % NN;
        #pragma unroll
        for (int k = 0; k < EMBD; k++) wp[k] = pw[k * NN + jp];
        pbv = pb[jp];
    }

    float w3[H2];                             // energy head, threads 256..261
    float b3v = 0.0f;
    if (tid >= 256 && tid < 256 + NN) {
        #pragma unroll
        for (int k = 0; k < H2; k++) w3[k] = fc3_w[k];
        b3v = fc3_b[0];
    }

    if (tid < NN * EMBD) sx[tid / EMBD][tid % EMBD] = x[tid];

    // ---- gumbels: path-independent, 30 threads in parallel with the loads ----
    // split(key(42),5) partitionable: keys[s] = tf((0,42),(0,s)) full pair.
    // random_bits: bits[j] = o0^o1 of tf(key,(0,j)).
    if (tid >= 352 && tid < 352 + (NN - 1) * NN) {
        int t = tid - 352, step = t / NN, j = t % NN;
        unsigned k0, k1, o0, o1;
        tf2x32(0u, 42u, 0u, (unsigned)step, k0, k1);
        tf2x32(k0, k1, 0u, (unsigned)j, o0, o1);
        g[step][j] = gumbel_from_bits(o0 ^ o1);
    }
    __syncthreads();

    // ---- h1 = relu(x @ fc1_w + b1): one elem per thread ----
    {
        float acc = b1v;
        #pragma unroll
        for (int k = 0; k < EMBD; k++) acc += sx[i1][k] * w1[k];
        h1s[i1][j1] = fmaxf(acc, 0.0f);
    }
    __syncthreads();

    // ---- h2 = relu(h1 @ fc2_w + b2) and raw path logits ----
    if (tid < NN * H2) {
        float acc = b2v;
        #pragma unroll
        for (int k = 0; k < H1; k++) acc += h1s[i2][k] * w2[k];
        h2s[i2][j2] = fmaxf(acc, 0.0f);
    }
    if (tid >= 192 && tid < 192 + NN * NN) {
        int t = tid - 192, i = t / NN, j = t % NN;
        float acc = pbv;
        #pragma unroll
        for (int k = 0; k < EMBD; k++) acc += sx[i][k] * wp[k];
        logp[i][j] = acc;
    }
    __syncthreads();

    // ---- energy head + row log_softmax ----
    if (tid >= 256 && tid < 256 + NN) {
        int i = tid - 256;
        float acc = b3v;
        #pragma unroll
        for (int k = 0; k < H2; k++) acc += h2s[i][k] * w3[k];
        out[i] = fmaxf(acc, 0.0f) + log1pf(expf(-fabsf(acc)));   // softplus
    }
    if (tid >= 32 && tid < 32 + NN) {
        int i = tid - 32;
        float m = logp[i][0];
        #pragma unroll
        for (int j = 1; j < NN; j++) m = fmaxf(m, logp[i][j]);
        float s = 0.0f;
        #pragma unroll
        for (int j = 0; j < NN; j++) s += expf(logp[i][j] - m);
        float lse = logf(s);
        #pragma unroll
        for (int j = 0; j < NN; j++) logp[i][j] = logp[i][j] - m - lse;
    }
    __syncthreads();

    // ---- vall[step][cur][j] = logp[cur][j] + g[step][j] (180 threads) ----
    if (tid < (NN - 1) * NN * NN) {
        int s = tid / (NN * NN), r = (tid / NN) % NN, j = tid % NN;
        vall[s][r][j] = logp[r][j] + g[s][j];
    }
    __syncthreads();

    // ---- serial masked argmax, now just table lookups ----
    if (tid == 0) {
        bool mask[NN];
        mask[0] = false;
        #pragma unroll
        for (int j = 1; j < NN; j++) mask[j] = true;

        int cur = 0;
        out[NN] = 0.0f;                        // path[0] = 0
        for (int step = 0; step < NN - 1; step++) {
            float best = -__int_as_float(0x7f800000);
            int bestj = 0;
            bool have = false;
            #pragma unroll
            for (int j = 0; j < NN; j++) {
                if (!mask[j]) continue;        // where(mask,.,-inf)+g = -inf
                float v = vall[step][cur][j];
                if (!have || v > best) { best = v; bestj = j; have = true; }
            }
            cur = bestj;
            mask[bestj] = false;
            out[NN + 1 + step] = (float)bestj;
        }
        out[2 * NN] = 0.0f;                    // path[N] = 0
    }
}

extern "C" void kernel_launch(void* const* d_in, const int* in_sizes, int n_in,
                              void* d_out, int out_size) {
    const float* x     = (const float*)d_in[0];
    // d_in[1] = path (int32, unused by the forward outputs)
    const float* fc1_w = (const float*)d_in[2];
    const float* fc1_b = (const float*)d_in[3];
    const float* fc2_w = (const float*)d_in[4];
    const float* fc2_b = (const float*)d_in[5];
    const float* fc3_w = (const float*)d_in[6];
    const float* fc3_b = (const float*)d_in[7];
    const float* pw    = (const float*)d_in[8];
    const float* pb    = (const float*)d_in[9];
    float* out = (float*)d_out;

    node2vec_kernel<<<1, 384>>>(x, fc1_w, fc1_b, fc2_w, fc2_b,
                                fc3_w, fc3_b, pw, pb, out);
}

// round 4
// speedup vs baseline: 1.5926x; 1.0093x over previous
#include <cuda_runtime.h>

// Node2VecModel: N=6, EMB=32. One latency-bound kernel, warp-specialized:
//   warps 0-5  (bar 1): energy MLP -> out[0..5]
//   warps 6-11 (bar 2): path logits -> log_softmax -> gumbel-max -> out[6..12]
// The two chains share nothing and run fully overlapped.

#define NN   6
#define EMBD 32
#define H1   64
#define H2   32

__device__ __forceinline__ void tf2x32(unsigned k0, unsigned k1,
                                       unsigned x0, unsigned x1,
                                       unsigned &o0, unsigned &o1) {
    unsigned ks2 = k0 ^ k1 ^ 0x1BD11BDAu;
    x0 += k0; x1 += k1;
#define TF_RND(r) { x0 += x1; x1 = (x1 << (r)) | (x1 >> (32 - (r))); x1 ^= x0; }
    TF_RND(13) TF_RND(15) TF_RND(26) TF_RND(6)
    x0 += k1;  x1 += ks2 + 1u;
    TF_RND(17) TF_RND(29) TF_RND(16) TF_RND(24)
    x0 += ks2; x1 += k0 + 2u;
    TF_RND(13) TF_RND(15) TF_RND(26) TF_RND(6)
    x0 += k0;  x1 += k1 + 3u;
    TF_RND(17) TF_RND(29) TF_RND(16) TF_RND(24)
    x0 += k1;  x1 += ks2 + 4u;
    TF_RND(13) TF_RND(15) TF_RND(26) TF_RND(6)
    x0 += ks2; x1 += k0 + 5u;
#undef TF_RND
    o0 = x0; o1 = x1;
}

// JAX uniform(tiny,1) fp32 -> gumbel. (1-tiny) rounds to 1.0f => u = max(tiny, f+tiny).
__device__ __forceinline__ float gumbel_from_bits(unsigned b) {
    const float tiny = 1.1754943508222875e-38f;
    float f = __uint_as_float((b >> 9) | 0x3f800000u) - 1.0f;
    float u = fmaxf(__fadd_rn(f, tiny), tiny);
    return -logf(-logf(u));
}

#define BARSYNC(id) asm volatile("bar.sync %0, 192;" :: "r"(id) : "memory")

__global__ __launch_bounds__(384, 1)
void node2vec_kernel(const float* __restrict__ x,
                     const float* __restrict__ fc1_w, const float* __restrict__ fc1_b,
                     const float* __restrict__ fc2_w, const float* __restrict__ fc2_b,
                     const float* __restrict__ fc3_w, const float* __restrict__ fc3_b,
                     const float* __restrict__ pw,    const float* __restrict__ pb,
                     float* __restrict__ out) {
    __shared__ float sxE[NN * EMBD];
    __shared__ float h1s[NN][H1];
    __shared__ float h2s[NN][H2];
    __shared__ float logp[NN][NN];
    __shared__ float g[NN - 1][NN];

    int tid = threadIdx.x;

    if (tid < 192) {
        // ================= ENERGY CHAIN (warps 0-5, bar.sync 1) =================
        int j1 = tid & 63, r1 = tid >> 6;          // h1 elems (r1,j1) and (r1+3,j1)
        float w1[EMBD];
        #pragma unroll
        for (int k = 0; k < EMBD; k++) w1[k] = fc1_w[k * H1 + j1];
        float b1v = fc1_b[j1];

        int i2 = tid >> 5, j2 = tid & 31;          // h2 elem (i2,j2)
        float w2[H1];
        #pragma unroll
        for (int k = 0; k < H1; k++) w2[k] = fc2_w[k * H2 + j2];
        float b2v = fc2_b[j2];

        float w3[H2]; float b3v = 0.0f;
        if (tid < NN) {
            #pragma unroll
            for (int k = 0; k < H2; k++) w3[k] = fc3_w[k];
            b3v = fc3_b[0];
        }

        sxE[tid] = x[tid];                          // stage x (192 floats)
        BARSYNC(1);

        // h1 = relu(x @ fc1_w + b1): 2 rows per thread, independent accumulators
        {
            float a0 = b1v, a1 = b1v;
            #pragma unroll
            for (int k = 0; k < EMBD; k++) {
                a0 += sxE[r1 * EMBD + k]       * w1[k];
                a1 += sxE[(r1 + 3) * EMBD + k] * w1[k];
            }
            h1s[r1][j1]     = fmaxf(a0, 0.0f);
            h1s[r1 + 3][j1] = fmaxf(a1, 0.0f);
        }
        BARSYNC(1);

        // h2 = relu(h1 @ fc2_w + b2): 4-way split accumulation
        {
            float c0 = 0.f, c1 = 0.f, c2 = 0.f, c3 = 0.f;
            #pragma unroll
            for (int k = 0; k < H1; k += 4) {
                c0 += h1s[i2][k]     * w2[k];
                c1 += h1s[i2][k + 1] * w2[k + 1];
                c2 += h1s[i2][k + 2] * w2[k + 2];
                c3 += h1s[i2][k + 3] * w2[k + 3];
            }
            h2s[i2][j2] = fmaxf(b2v + ((c0 + c1) + (c2 + c3)), 0.0f);
        }
        BARSYNC(1);

        // energy head + softplus
        if (tid < NN) {
            float c0 = 0.f, c1 = 0.f, c2 = 0.f, c3 = 0.f;
            #pragma unroll
            for (int k = 0; k < H2; k += 4) {
                c0 += h2s[tid][k]     * w3[k];
                c1 += h2s[tid][k + 1] * w3[k + 1];
                c2 += h2s[tid][k + 2] * w3[k + 2];
                c3 += h2s[tid][k + 3] * w3[k + 3];
            }
            float acc = b3v + ((c0 + c1) + (c2 + c3));
            out[tid] = fmaxf(acc, 0.0f) + log1pf(expf(-fabsf(acc)));
        }
    } else {
        // ================= PATH CHAIN (warps 6-11, bar.sync 2) =================
        int t = tid - 192;

        // gumbels (warp 11, 30 threads): fully path-independent, overlap with LDGs
        if (t >= 160 && t < 160 + (NN - 1) * NN) {
            int u = t - 160, step = u / NN, j = u % NN;
            unsigned k0, k1, o0, o1;
            tf2x32(0u, 42u, 0u, (unsigned)step, k0, k1);   // split(key(42),5)[step]
            tf2x32(k0, k1, 0u, (unsigned)j, o0, o1);       // random_bits fold
            g[step][j] = gumbel_from_bits(o0 ^ o1);
        }

        // logits = x @ path_fc_w + path_fc_b  (36 threads, direct LDG of x row)
        if (t < NN * NN) {
            int i = t / NN, j = t % NN;
            float acc = pb[j];
            #pragma unroll
            for (int k = 0; k < EMBD; k++)
                acc += x[i * EMBD + k] * pw[k * NN + j];
            logp[i][j] = acc;                       // raw logits
        }
        BARSYNC(2);

        // per-row log_softmax (6 threads)
        if (t < NN) {
            float m = logp[t][0];
            #pragma unroll
            for (int j = 1; j < NN; j++) m = fmaxf(m, logp[t][j]);
            float s = 0.0f;
            #pragma unroll
            for (int j = 0; j < NN; j++) s += expf(logp[t][j] - m);
            float lse = logf(s);
            #pragma unroll
            for (int j = 0; j < NN; j++) logp[t][j] = logp[t][j] - m - lse;
        }
        BARSYNC(2);

        // serial gumbel-max walk (thread 192)
        if (t == 0) {
            bool mask[NN];
            mask[0] = false;
            #pragma unroll
            for (int j = 1; j < NN; j++) mask[j] = true;

            int cur = 0;
            out[NN] = 0.0f;                         // path[0] = 0
            for (int step = 0; step < NN - 1; step++) {
                float best = -__int_as_float(0x7f800000);
                int bestj = 0;
                bool have = false;
                #pragma unroll
                for (int j = 0; j < NN; j++) {
                    if (!mask[j]) continue;         // where(mask,.,-inf)+g = -inf
                    float v = logp[cur][j] + g[step][j];
                    if (!have || v > best) { best = v; bestj = j; have = true; }
                }
                cur = bestj;
                mask[bestj] = false;
                out[NN + 1 + step] = (float)bestj;
            }
            out[2 * NN] = 0.0f;                     // path[N] = 0
        }
    }
}

extern "C" void kernel_launch(void* const* d_in, const int* in_sizes, int n_in,
                              void* d_out, int out_size) {
    const float* x     = (const float*)d_in[0];
    // d_in[1] = path (int32, unused by the forward outputs)
    const float* fc1_w = (const float*)d_in[2];
    const float* fc1_b = (const float*)d_in[3];
    const float* fc2_w = (const float*)d_in[4];
    const float* fc2_b = (const float*)d_in[5];
    const float* fc3_w = (const float*)d_in[6];
    const float* fc3_b = (const float*)d_in[7];
    const float* pw    = (const float*)d_in[8];
    const float* pb    = (const float*)d_in[9];
    float* out = (float*)d_out;

    node2vec_kernel<<<1, 384>>>(x, fc1_w, fc1_b, fc2_w, fc2_b,
                                fc3_w, fc3_b, pw, pb, out);
}